// round 6
// baseline (speedup 1.0000x reference)
#include <cuda_runtime.h>
#include <cstddef>
#include <cstdint>

// ErbNorm: per-(b,f) EMA normalization scan over T.
//   mu_t  = a*mu_{t-1} + (1-a)*x_t
//   var_t = a*var_{t-1} + (1-a)*(x_t - mu_t)^2
//   out_t = (x_t - mu_t) / (sqrt(var_t) + eps)
//
// Round 6: both read and write streams via cp.async.bulk in 8KB contiguous
// bursts (one per 32-step group per CTA), mbarrier-completed reads, bulk_group
// stores from a double-buffered smem staging tile. One 64-thread CTA per batch
// row; thread tid owns feature lane f=tid. Scaled recurrence:
//   v' = var/(beta*alpha^2):  v'_t = a*v'_{t-1} + d0^2,  d0 = x - mu_{t-1}
//   mu_t = mu_{t-1} + beta*d0
//   out  = (C*d0)*rsqrt(v'_t),  C = alpha/sqrt(beta*alpha^2) = 10.0

#ifndef ERB_T
#define ERB_T 4000
#endif
#define ERB_F     64
#define ERB_G     32                        // timesteps per group
#define ERB_NSL   8                         // ring slots
#define SLOT_B    (ERB_G * ERB_F * 4)       // 8192 bytes per slot
#define SLOT_FL   (ERB_G * ERB_F)           // 2048 floats per slot
#define RING_B    (ERB_NSL * SLOT_B)        // 65536
#define OBUF_B    (2 * SLOT_B)              // 16384
#define SMEM_DYN  (RING_B + OBUF_B)         // 81920

__device__ __forceinline__ uint32_t smem_u32(const void* p) {
    return (uint32_t)__cvta_generic_to_shared(p);
}
__device__ __forceinline__ void mbar_init(uint32_t a, uint32_t cnt) {
    asm volatile("mbarrier.init.shared.b64 [%0], %1;" :: "r"(a), "r"(cnt) : "memory");
}
__device__ __forceinline__ void mbar_expect_tx(uint32_t a, uint32_t bytes) {
    asm volatile("mbarrier.arrive.expect_tx.shared.b64 _, [%0], %1;"
                 :: "r"(a), "r"(bytes) : "memory");
}
__device__ __forceinline__ void mbar_wait(uint32_t a, uint32_t parity) {
    asm volatile(
        "{\n\t.reg .pred P;\n"
        "W%=:\n\t"
        "mbarrier.try_wait.parity.shared.b64 P, [%0], %1;\n\t"
        "@P bra D%=;\n\t"
        "bra W%=;\n"
        "D%=:\n\t}"
        :: "r"(a), "r"(parity) : "memory");
}
__device__ __forceinline__ void bulk_g2s(uint32_t sdst, const void* gsrc,
                                         uint32_t bytes, uint32_t mbar) {
    asm volatile(
        "cp.async.bulk.shared::cluster.global.mbarrier::complete_tx::bytes "
        "[%0], [%1], %2, [%3];"
        :: "r"(sdst), "l"(gsrc), "r"(bytes), "r"(mbar) : "memory");
}
__device__ __forceinline__ void bulk_s2g(void* gdst, uint32_t ssrc, uint32_t bytes) {
    asm volatile("cp.async.bulk.global.shared::cta.bulk_group [%0], [%1], %2;"
                 :: "l"(gdst), "r"(ssrc), "r"(bytes) : "memory");
}
__device__ __forceinline__ void bulk_commit() {
    asm volatile("cp.async.bulk.commit_group;" ::: "memory");
}
__device__ __forceinline__ void bulk_wait_read1() {
    asm volatile("cp.async.bulk.wait_group.read 1;" ::: "memory");
}
__device__ __forceinline__ void bulk_wait_all() {
    asm volatile("cp.async.bulk.wait_group 0;" ::: "memory");
}
__device__ __forceinline__ void fence_async_shared() {
    asm volatile("fence.proxy.async.shared::cta;" ::: "memory");
}

__global__ void __launch_bounds__(64)
erbnorm_kernel(const float* __restrict__ x, float* __restrict__ out, int T)
{
    extern __shared__ __align__(128) char smem[];
    char* ring = smem;                 // 8 x 8KB input slots
    char* obuf = smem + RING_B;        // 2 x 8KB output staging
    __shared__ __align__(8) uint64_t mb[ERB_NSL];

    const int tid = threadIdx.x;       // 0..63 == feature lane f
    const int b   = blockIdx.x;

    const float alpha = 0.99f;
    const float beta  = (float)(1.0 - 0.99);
    const float C     = 10.0f;                      // alpha/sqrt(beta*alpha^2)
    const float step  = (float)((-90.0 - (-60.0)) / 63.0);

    float mu = fmaf((float)tid, step, -60.0f);
    float vp = 163248.648f;                         // 1600 / (beta*alpha^2)

    const size_t base = (size_t)b * (size_t)T * ERB_F;
    const float* gx = x   + base;
    float*       go = out + base;

    const int NG = T / ERB_G;                       // 125 groups

    // ---- init barriers + prologue fills (8 slots = 64KB in flight) ----
    if (tid == 0) {
        #pragma unroll
        for (int s = 0; s < ERB_NSL; ++s) mbar_init(smem_u32(&mb[s]), 1);
        // make mbarrier init visible to the async proxy before bulk ops
        fence_async_shared();
        #pragma unroll
        for (int s = 0; s < ERB_NSL; ++s) {
            uint32_t m = smem_u32(&mb[s]);
            mbar_expect_tx(m, SLOT_B);
            bulk_g2s(smem_u32(ring + s * SLOT_B), gx + (size_t)s * SLOT_FL,
                     SLOT_B, m);
        }
    }
    __syncthreads();

    int slot = 0, ph = 0;

    for (int g = 0; g < NG; ++g) {
        // Ensure the bulk store issued 2 groups ago has finished READING
        // obuf[g&1] before we overwrite it (<=1 store group left pending).
        if (tid == 0) bulk_wait_read1();
        // Wait for this group's input slot.
        mbar_wait(smem_u32(&mb[slot]), (uint32_t)ph);
        __syncthreads();   // broadcast tid0's wait_group guarantee to all

        const float* xs = (const float*)(ring + slot * SLOT_B);
        float*       ob = (float*)(obuf + (g & 1) * SLOT_B);

        #pragma unroll
        for (int i = 0; i < ERB_G; ++i) {
            float d0 = xs[i * ERB_F + tid] - mu;
            mu = fmaf(beta, d0, mu);
            vp = fmaf(alpha, vp, d0 * d0);
            ob[i * ERB_F + tid] = (C * d0) * rsqrtf(vp);
        }

        fence_async_shared();   // order our generic STS for the async proxy
        __syncthreads();        // all 64 threads' outputs staged

        if (tid == 0) {
            bulk_s2g(go + (size_t)g * SLOT_FL, smem_u32(ob), SLOT_B);
            bulk_commit();
            if (g + ERB_NSL < NG) {
                uint32_t m = smem_u32(&mb[slot]);
                mbar_expect_tx(m, SLOT_B);
                bulk_g2s(smem_u32(ring + slot * SLOT_B),
                         gx + (size_t)(g + ERB_NSL) * SLOT_FL, SLOT_B, m);
            }
        }

        if (++slot == ERB_NSL) { slot = 0; ph ^= 1; }
    }

    if (tid == 0) bulk_wait_all();   // drain pending bulk stores before exit
}

extern "C" void kernel_launch(void* const* d_in, const int* in_sizes, int n_in,
                              void* d_out, int out_size)
{
    const float* x = (const float*)d_in[0];
    float* out = (float*)d_out;

    const int T = ERB_T;                       // 4000
    const int B = in_sizes[0] / (T * ERB_F);   // 256

    cudaFuncSetAttribute(erbnorm_kernel,
                         cudaFuncAttributeMaxDynamicSharedMemorySize, SMEM_DYN);
    dim3 grid(B);       // one 64-thread CTA per batch row
    dim3 block(64);
    erbnorm_kernel<<<grid, block, SMEM_DYN>>>(x, out, T);
}

// round 7
// speedup vs baseline: 1.9806x; 1.9806x over previous
#include <cuda_runtime.h>
#include <cstddef>
#include <cstdint>

// ErbNorm: per-(b,f) EMA normalization scan over T.
//   mu_t  = a*mu_{t-1} + (1-a)*x_t
//   var_t = a*var_{t-1} + (1-a)*(x_t - mu_t)^2
//   out_t = (x_t - mu_t) / (sqrt(var_t) + eps)
//
// Round 7: R3 datapath (cp.async ring 8 slots x 16 steps x 128B per warp +
// register double-buffer, warp-autonomous), repacked as 128 CTAs x 4 warps so
// wave-1 placement gives exactly one CTA (4 warps) per SM -> no 4-vs-3
// warps/SM makespan skew. Warp w of CTA c owns stream idx=c*4+w -> (b, half).
// No CTA-level syncs; each warp runs its own ring with __syncwarp only.

#ifndef ERB_T
#define ERB_T 4000
#endif
#define ERB_F   64
#define ERB_G   16                   // timesteps per commit group
#define ERB_NGR 8                    // ring slots per warp
#define ERB_SLOT_FLOATS (ERB_G * 32)     // 512
#define ERB_SLOT_BYTES  (ERB_G * 128)    // 2048
#define ERB_RING_FLOATS (ERB_NGR * ERB_SLOT_FLOATS)  // 4096 floats = 16KB
#define ERB_SMEM_DYN    (4 * ERB_RING_FLOATS * 4)    // 64KB per CTA

__device__ __forceinline__ void cp_async16(uint32_t saddr, const void* gaddr) {
    asm volatile("cp.async.cg.shared.global [%0], [%1], 16;\n"
                 :: "r"(saddr), "l"(gaddr));
}
__device__ __forceinline__ void cp_commit() {
    asm volatile("cp.async.commit_group;\n");
}
__device__ __forceinline__ void cp_wait7() {
    asm volatile("cp.async.wait_group 7;\n");
}

__global__ void __launch_bounds__(128, 1)
erbnorm_kernel(const float* __restrict__ x, float* __restrict__ out, int T)
{
    extern __shared__ __align__(128) float smem[];   // 4 per-warp rings

    const int lane = threadIdx.x & 31;
    const int w    = threadIdx.x >> 5;               // warp in CTA
    const int idx  = blockIdx.x * 4 + w;             // global stream id
    const int b    = idx >> 1;
    const int half = idx & 1;
    const int f    = (half << 5) + lane;

    float* buf = smem + w * ERB_RING_FLOATS;         // this warp's 16KB ring

    const float alpha = 0.99f;
    const float beta  = (float)(1.0 - 0.99);
    const float kvar  = (float)((1.0 - 0.99) * 0.99 * 0.99);  // beta*alpha^2
    const float step  = (float)((-90.0 - (-60.0)) / 63.0);

    float mu  = fmaf((float)f, step, -60.0f);
    float var = 1600.0f;

    const size_t base = (size_t)b * (size_t)T * ERB_F + (size_t)(half << 5);

    // Cooperative load mapping: 8 lanes cover one 128B stage (4 rows each).
    const int r_off = lane >> 3;
    const int c_off = (lane & 7) * 4;

    const float* gsrc = x + base + (size_t)r_off * ERB_F + c_off;
    const uint32_t sbase =
        (uint32_t)__cvta_generic_to_shared(buf) + (uint32_t)(r_off * 128 + c_off * 4);

    // ---- prologue: fill all 8 slots ----
    {
        const float* p = gsrc;
        uint32_t sa = sbase;
        #pragma unroll
        for (int grp = 0; grp < ERB_NGR; ++grp) {
            #pragma unroll
            for (int r = 0; r < 4; ++r)
                cp_async16(sa + (uint32_t)(r * 4 * 128), p + (size_t)(r * 4) * ERB_F);
            cp_commit();
            sa += ERB_SLOT_BYTES;
            p  += (size_t)ERB_G * ERB_F;
        }
    }

    const int NG = T / ERB_G;                 // 250 (even)
    const float* sp   = buf + lane;           // this lane's smem column
    float*       q    = out + base + lane;
    const float* pref = gsrc + (size_t)ERB_NGR * ERB_G * ERB_F;

    float A[ERB_G], Bv[ERB_G];

    // Load group 0 into A.
    cp_wait7();
    __syncwarp();
    #pragma unroll
    for (int i = 0; i < ERB_G; ++i) A[i] = sp[i * 32];

#define ERB_BODY(CUR, NXT, g)                                                  \
    {                                                                          \
        /* refill slot (g & 7) with group (g + 8), fire-and-forget */          \
        if ((g) + ERB_NGR < NG) {                                              \
            uint32_t sa = sbase + (uint32_t)(((g) & 7) * ERB_SLOT_BYTES);      \
            _Pragma("unroll")                                                  \
            for (int r = 0; r < 4; ++r)                                        \
                cp_async16(sa + (uint32_t)(r * 4 * 128),                       \
                           pref + (size_t)(r * 4) * ERB_F);                    \
            pref += (size_t)ERB_G * ERB_F;                                     \
        }                                                                      \
        cp_commit();                                                           \
        /* wait for group g+1 and pull it into NXT */                          \
        cp_wait7();                                                            \
        __syncwarp();                                                          \
        {                                                                      \
            const float* sn = sp + (((g) + 1) & 7) * ERB_SLOT_FLOATS;          \
            _Pragma("unroll")                                                  \
            for (int i = 0; i < ERB_G; ++i) NXT[i] = sn[i * 32];               \
        }                                                                      \
        /* scan group g from CUR */                                            \
        _Pragma("unroll")                                                      \
        for (int i = 0; i < ERB_G; ++i) {                                      \
            float d0 = CUR[i] - mu;                                            \
            mu = fmaf(beta, d0, mu);                                           \
            float d = alpha * d0;                                              \
            var = fmaf(alpha, var, (kvar * d0) * d0);                          \
            __stcs(q + i * ERB_F, d * rsqrtf(var));                            \
        }                                                                      \
        q += ERB_G * ERB_F;                                                    \
    }

    for (int g = 0; g < NG; g += 2) {
        ERB_BODY(A, Bv, g)
        ERB_BODY(Bv, A, g + 1)
    }
#undef ERB_BODY
}

extern "C" void kernel_launch(void* const* d_in, const int* in_sizes, int n_in,
                              void* d_out, int out_size)
{
    const float* x = (const float*)d_in[0];
    float* out = (float*)d_out;

    const int T = ERB_T;                       // 4000
    const int B = in_sizes[0] / (T * ERB_F);   // 256

    cudaFuncSetAttribute(erbnorm_kernel,
                         cudaFuncAttributeMaxDynamicSharedMemorySize,
                         ERB_SMEM_DYN);
    dim3 grid(B / 2);   // 128 CTAs x 4 warps = 512 streams
    dim3 block(128);
    erbnorm_kernel<<<grid, block, ERB_SMEM_DYN>>>(x, out, T);
}